// round 9
// baseline (speedup 1.0000x reference)
#include <cuda_runtime.h>
#include <math.h>

#define STEPF   0.1f
#define MAXL    2048
#define MAXNS   64
#define MAXNP   128
#define DELAY_N 30
#define TPB     64

typedef unsigned long long u64;

__device__ float  g_aif[MAXL];
__device__ float4 g_p4[MAXNP];     // per piece: (A, A, slope, slope)
__device__ float2 g_ex[MAXNS];     // per output: dup'd aif[12j+1]
__device__ int    g_idx[MAXNS];
__device__ int    g_L;
__device__ int    g_aligned;
__device__ u64    g_dmask;

__device__ __forceinline__ u64 fma2(u64 a, u64 b, u64 c) {
    u64 d; asm("fma.rn.f32x2 %0, %1, %2, %3;" : "=l"(d) : "l"(a), "l"(b), "l"(c)); return d;
}
__device__ __forceinline__ u64 mul2(u64 a, u64 b) {
    u64 d; asm("mul.rn.f32x2 %0, %1, %2;" : "=l"(d) : "l"(a), "l"(b)); return d;
}
__device__ __forceinline__ u64 pack2(float lo, float hi) {
    u64 d; asm("mov.b64 %0, {%1, %2};" : "=l"(d) : "f"(lo), "f"(hi)); return d;
}
__device__ __forceinline__ u64 dup2(float v) { return pack2(v, v); }
__device__ __forceinline__ void unpack2(u64 v, float& lo, float& hi) {
    asm("mov.b64 {%0, %1}, %2;" : "=f"(lo), "=f"(hi) : "l"(v));
}
__device__ __forceinline__ float rcpf(float x) {
    float r; asm("rcp.approx.f32 %0, %1;" : "=f"(r) : "f"(x)); return r;
}

__device__ __forceinline__ float interp_at(float t, const float* st, const float* cp, int ns) {
    if (t <= st[0]) return cp[0];
    if (t >= st[ns - 1]) return cp[ns - 1];
    int lo = 0, hi = ns - 1;
    while (lo + 1 < hi) { int mid = (lo + hi) >> 1; if (st[mid] <= t) lo = mid; else hi = mid; }
    return cp[lo] + (t - st[lo]) * (cp[lo + 1] - cp[lo]) / (st[lo + 1] - st[lo]);
}

// ---------------------------------------------------------------------------
__global__ void dce_prep_kernel(const float* __restrict__ sample_time,
                                const float* __restrict__ Cp, int ns)
{
    __shared__ float s_st[MAXNS], s_cp[MAXNS], s_av[MAXNP + 1];
    __shared__ int s_ok;
    __shared__ unsigned int s_dm[2];
    const int tid = threadIdx.x;
    if (tid == 0) { s_ok = 1; s_dm[0] = 0; s_dm[1] = 0; }
    for (int j = tid; j < ns && j < MAXNS; j += blockDim.x) { s_st[j] = sample_time[j]; s_cp[j] = Cp[j]; }
    __syncthreads();

    const int Ltrue = (int)llrint((double)s_st[ns - 1] / 0.1) + 1;
    const int L = Ltrue < MAXL ? Ltrue : MAXL;
    if (tid == 0) g_L = L;

    for (int j = tid; j < ns && j < MAXNS; j += blockDim.x) {
        const float st = s_st[j];
        int lo = 0, hi = L;
        while (lo < hi) { int mid = (lo + hi) >> 1; if ((float)mid * STEPF < st) lo = mid + 1; else hi = mid; }
        lo = lo < (L - 1) ? lo : (L - 1);
        g_idx[j] = lo;
        const int d = lo - 12 * j;
        if (d < 0 || d > 1) s_ok = 0;
        else if (d == 1) atomicOr(&s_dm[j >> 5], 1u << (j & 31));
    }
    __syncthreads();

    const int NP = 2 * ns - 7;
    const int aligned = s_ok && ns >= 5 && ns <= MAXNS && NP < MAXNP && Ltrue == 12 * (ns - 1) + 1;
    if (tid == 0) { g_aligned = aligned; g_dmask = ((u64)s_dm[1] << 32) | (u64)s_dm[0]; }

    if (aligned) {
        for (int i = tid; i <= NP; i += blockDim.x)
            s_av[i] = interp_at((float)(6 * i) * STEPF, s_st, s_cp, ns);
        __syncthreads();
        for (int i = tid; i < NP; i += blockDim.x) {
            const float A = s_av[i];
            const float sl = (s_av[i + 1] - A) * (1.f / 6.f);
            g_p4[i] = make_float4(A, A, sl, sl);
        }
        for (int j = tid; j < ns && j < MAXNS; j += blockDim.x) {
            const int m = 12 * j + 1;
            float v = 0.f;
            if (m >= DELAY_N && m < L) v = interp_at((float)(m - DELAY_N) * STEPF, s_st, s_cp, ns);
            g_ex[j] = make_float2(v, v);
        }
    } else {
        for (int i = tid; i < L; i += blockDim.x)
            g_aif[i] = (i >= DELAY_N) ? interp_at((float)(i - DELAY_N) * STEPF, s_st, s_cp, ns) : 0.f;
    }
}

// ---------------------------------------------------------------------------
struct PixCtx {
    u64 R, ZAB;
    float M0t, bse, c0, c1, c2, c3, cosfa;
};

#define SIG_OF(ctx, Sv, dst) do {                                              \
    float _zl, _zh; unpack2(mul2((Sv), (ctx).ZAB), _zl, _zh);                  \
    const float _z = _zl + _zh;                                                \
    const float _e = fmaf(fmaf(fmaf(_z, (ctx).c3, (ctx).c2), _z, (ctx).c1), _z, (ctx).c0); \
    (dst) = fmaf(fmaf(-(ctx).M0t, _e, (ctx).M0t), rcpf(fmaf(-(ctx).cosfa, _e, 1.f)), (ctx).bse); \
} while (0)

template <int NPAIRS>
__device__ __forceinline__ void run_aligned(const PixCtx& ctx,
                                            const float4* __restrict__ s_p4,
                                            const u64* __restrict__ exq,
                                            u64 dmask, int NP,
                                            float* optr, size_t stp)
{
    const u64 ONE = pack2(1.f, 1.f);
    const u64 R = ctx.R;
    const u64 R2 = mul2(R, R), R6 = mul2(mul2(R2, R2), R2);
    u64 G6 = fma2(R, ONE, ONE);
    G6 = fma2(G6, R, ONE); G6 = fma2(G6, R, ONE);
    G6 = fma2(G6, R, ONE); G6 = fma2(G6, R, ONE);            // 1+r+..+r^5
    u64 H6 = fma2(R, ONE, pack2(2.f, 2.f));
    H6 = fma2(H6, R, pack2(3.f, 3.f)); H6 = fma2(H6, R, pack2(4.f, 4.f));
    H6 = fma2(H6, R, pack2(5.f, 5.f)); H6 = fma2(H6, R, pack2(6.f, 6.f)); // Σ i·r^(6-i)

    float sig0; SIG_OF(ctx, 0ull, sig0);
    optr[0] = sig0; optr[stp] = sig0; optr[2 * stp] = sig0;
    optr += 3 * stp;

    u64 dm = dmask >> 3;                       // bit 0 -> output j=3
    float4 p00 = s_p4[0];
    u64 S = pack2(p00.x, p00.y);               // dup'd aif[30]

    #pragma unroll 8
    for (int k = 0; k < NPAIRS; ++k) {
        const float4 p0 = s_p4[2 * k];         // one LDS.128 each
        const float4 p1 = s_p4[2 * k + 1];
        const u64 A0 = pack2(p0.x, p0.y), L0 = pack2(p0.z, p0.w);
        const u64 A1 = pack2(p1.x, p1.y), L1 = pack2(p1.z, p1.w);
        S = fma2(S, R6, fma2(L0, H6, mul2(A0, G6)));
        u64 Se = S;
        if ((dm >> k) & 1ull) Se = fma2(S, R, exq[k + 3]);
        float sig; SIG_OF(ctx, Se, sig);
        *optr = sig; optr += stp;
        S = fma2(S, R6, fma2(L1, H6, mul2(A1, G6)));
    }
    const float4 pn = s_p4[NP - 1];
    const u64 An = pack2(pn.x, pn.y), Ln = pack2(pn.z, pn.w);
    S = fma2(S, R6, fma2(Ln, H6, mul2(An, G6)));
    u64 Se = S;
    if ((dm >> NPAIRS) & 1ull) Se = fma2(S, R, exq[NPAIRS + 3]);
    float sigl; SIG_OF(ctx, Se, sigl);
    *optr = sigl;
}

__global__ void __launch_bounds__(TPB)
dce_main_kernel(const float* __restrict__ param, float* __restrict__ out, int npix, int ns)
{
    __shared__ __align__(16) float4 s_p4[MAXNP];
    __shared__ __align__(8)  float2 s_ex[MAXNS];
    __shared__ float s_aif[MAXL];
    __shared__ int   s_idx[MAXNS];

    const int tid = threadIdx.x;
    const int pix = blockIdx.x * TPB + tid;
    const int p   = pix < npix ? pix : 0;

    // ---- per-pixel prologue: independent of prep results (PDL overlap) ----
    const float ve  = param[p];
    const float vp  = param[npix + p];
    const float fpp = param[2 * npix + p];
    const float ps  = param[3 * npix + p];

    const float Te = ve / ps;
    const float T  = (vp + ve) / fpp;
    const float Tc = vp / fpp;
    const float s  = T + Te;
    const float disc = sqrtf(fmaxf(s * s - 4.f * Tc * Te, 0.f));
    const float inv2 = 1.f / (2.f * Tc * Te);
    const float thp = (s + disc) * inv2;
    const float thm = (s - disc) * inv2;

    const float rm = expf(-thm * STEPF);
    const float rp = expf(-thp * STEPF);

    PixCtx ctx;
    ctx.R = pack2(rm, rp);
    ctx.cosfa = 0.98480775301220806f;
    const float E1 = expf(-0.00487f);
    ctx.M0t = 100.f * (1.f - ctx.cosfa * E1) / (1.f - E1);
    ctx.bse = 100.f - ctx.M0t * (1.f - E1) / (1.f - E1 * ctx.cosfa);
    ctx.c0 = E1; ctx.c1 = E1; ctx.c2 = E1 * 0.5f; ctx.c3 = E1 * (1.f / 6.f);

    // ---- wait for prep, then stage its outputs ----
    cudaGridDependencySynchronize();

    const int aligned = g_aligned;
    const int L  = g_L;
    const int NP = 2 * ns - 7;

    if (aligned) {
        for (int i = tid; i < NP; i += TPB) s_p4[i] = g_p4[i];
        for (int j = tid; j < ns && j < MAXNS; j += TPB) s_ex[j] = g_ex[j];
    } else {
        for (int i = tid; i < L; i += TPB) s_aif[i] = g_aif[i];
        for (int j = tid; j < ns && j < MAXNS; j += TPB) s_idx[j] = g_idx[j];
    }
    __syncthreads();

    if (pix >= npix) return;

    // L-dependent part of the prologue
    const float Lf = (float)L;
    const float SEm = (-expm1f(-thm * STEPF * Lf)) / (-expm1f(-thm * STEPF));
    const float SEp = (-expm1f(-thp * STEPF * Lf)) / (-expm1f(-thp * STEPF));
    const float cmv = 1.f - Te * thm;
    const float cpc = Te * thp - 1.f;
    const float inv_she = 1.f / (SEm - SEp);
    const float inv_shp = 1.f / fmaf(cmv, SEm, cpc * SEp);
    const float alpha = vp * inv_shp * cmv + ve * inv_she;
    const float beta  = vp * inv_shp * cpc - ve * inv_she;
    const float Kz    = -(0.00487f * 4.3f);
    ctx.ZAB = pack2(Kz * alpha, Kz * beta);

    float* optr = out + pix;
    const size_t stp = (size_t)npix;
    const u64* exq = reinterpret_cast<const u64*>(s_ex);

    if (aligned) {
        const int npairs = ns - 4;
        if (npairs == 46) {
            run_aligned<46>(ctx, s_p4, exq, g_dmask, NP, optr, stp);
        } else {
            // generic aligned loop (runtime trip count)
            const u64 ONE = pack2(1.f, 1.f);
            const u64 R2 = mul2(ctx.R, ctx.R), R6 = mul2(mul2(R2, R2), R2);
            u64 G6 = fma2(ctx.R, ONE, ONE);
            G6 = fma2(G6, ctx.R, ONE); G6 = fma2(G6, ctx.R, ONE);
            G6 = fma2(G6, ctx.R, ONE); G6 = fma2(G6, ctx.R, ONE);
            u64 H6 = fma2(ctx.R, ONE, pack2(2.f, 2.f));
            H6 = fma2(H6, ctx.R, pack2(3.f, 3.f)); H6 = fma2(H6, ctx.R, pack2(4.f, 4.f));
            H6 = fma2(H6, ctx.R, pack2(5.f, 5.f)); H6 = fma2(H6, ctx.R, pack2(6.f, 6.f));

            float sig0; SIG_OF(ctx, 0ull, sig0);
            optr[0] = sig0; optr[stp] = sig0; optr[2 * stp] = sig0;
            optr += 3 * stp;

            u64 dm = g_dmask >> 3;
            float4 p00 = s_p4[0];
            u64 S = pack2(p00.x, p00.y);
            for (int k = 0; k < npairs; ++k) {
                const float4 p0 = s_p4[2 * k];
                const float4 p1 = s_p4[2 * k + 1];
                const u64 A0 = pack2(p0.x, p0.y), L0 = pack2(p0.z, p0.w);
                const u64 A1 = pack2(p1.x, p1.y), L1 = pack2(p1.z, p1.w);
                S = fma2(S, R6, fma2(L0, H6, mul2(A0, G6)));
                u64 Se = S;
                if (dm & 1ull) Se = fma2(S, ctx.R, exq[k + 3]);
                dm >>= 1;
                float sig; SIG_OF(ctx, Se, sig);
                *optr = sig; optr += stp;
                S = fma2(S, R6, fma2(L1, H6, mul2(A1, G6)));
            }
            const float4 pn = s_p4[NP - 1];
            S = fma2(S, R6, fma2(pack2(pn.z, pn.w), H6, mul2(pack2(pn.x, pn.y), G6)));
            u64 Se = S;
            if (dm & 1ull) Se = fma2(S, ctx.R, exq[ns - 1]);
            float sigl; SIG_OF(ctx, Se, sigl);
            *optr = sigl;
        }
    } else {
        u64 S = 0ull;
        int m = 0;
        for (int j = 0; j < ns; ++j) {
            const int target = s_idx[j];
            #pragma unroll 4
            for (; m <= target; ++m) S = fma2(S, ctx.R, dup2(s_aif[m]));
            float sig; SIG_OF(ctx, S, sig);
            *optr = sig; optr += stp;
        }
    }
}

extern "C" void kernel_launch(void* const* d_in, const int* in_sizes, int n_in,
                              void* d_out, int out_size)
{
    const float* param       = (const float*)d_in[0];
    const float* sample_time = (const float*)d_in[1];
    const float* Cp          = (const float*)d_in[2];
    float* out = (float*)d_out;

    const int ns   = in_sizes[1];
    const int npix = in_sizes[0] / 4;

    dce_prep_kernel<<<1, 128>>>(sample_time, Cp, ns);

    // main kernel with programmatic dependent launch: prologue overlaps prep
    cudaLaunchConfig_t cfg = {};
    cfg.gridDim  = dim3((npix + TPB - 1) / TPB, 1, 1);
    cfg.blockDim = dim3(TPB, 1, 1);
    cudaLaunchAttribute attrs[1];
    attrs[0].id = cudaLaunchAttributeProgrammaticStreamSerialization;
    attrs[0].val.programmaticStreamSerializationAllowed = 1;
    cfg.attrs = attrs;
    cfg.numAttrs = 1;
    cudaLaunchKernelEx(&cfg, dce_main_kernel, param, out, npix, ns);
}

// round 10
// speedup vs baseline: 1.0135x; 1.0135x over previous
#include <cuda_runtime.h>
#include <math.h>

#define STEPF   0.1f
#define MAXL    2048
#define MAXNS   64
#define MAXNP   128
#define DELAY_N 30
#define TPB     64

typedef unsigned long long u64;

__device__ __forceinline__ u64 fma2(u64 a, u64 b, u64 c) {
    u64 d; asm("fma.rn.f32x2 %0, %1, %2, %3;" : "=l"(d) : "l"(a), "l"(b), "l"(c)); return d;
}
__device__ __forceinline__ u64 mul2(u64 a, u64 b) {
    u64 d; asm("mul.rn.f32x2 %0, %1, %2;" : "=l"(d) : "l"(a), "l"(b)); return d;
}
__device__ __forceinline__ u64 pack2(float lo, float hi) {
    u64 d; asm("mov.b64 %0, {%1, %2};" : "=l"(d) : "f"(lo), "f"(hi)); return d;
}
__device__ __forceinline__ u64 dup2(float v) { return pack2(v, v); }
__device__ __forceinline__ void unpack2(u64 v, float& lo, float& hi) {
    asm("mov.b64 {%0, %1}, %2;" : "=f"(lo), "=f"(hi) : "l"(v));
}
__device__ __forceinline__ float rcpf(float x) {
    float r; asm("rcp.approx.f32 %0, %1;" : "=f"(r) : "f"(x)); return r;
}

__device__ __forceinline__ float interp_at(float t, const float* st, const float* cp, int ns) {
    if (t <= st[0]) return cp[0];
    if (t >= st[ns - 1]) return cp[ns - 1];
    int lo = 0, hi = ns - 1;
    while (lo + 1 < hi) { int mid = (lo + hi) >> 1; if (st[mid] <= t) lo = mid; else hi = mid; }
    return cp[lo] + (t - st[lo]) * (cp[lo + 1] - cp[lo]) / (st[lo + 1] - st[lo]);
}

struct PixCtx {
    u64 R, ZAB;
    float M0t, bse, c0, c1, c2, c3, cosfa;
};

#define SIG_OF(ctx, Sv, dst) do {                                              \
    float _zl, _zh; unpack2(mul2((Sv), (ctx).ZAB), _zl, _zh);                  \
    const float _z = _zl + _zh;                                                \
    const float _e = fmaf(fmaf(fmaf(_z, (ctx).c3, (ctx).c2), _z, (ctx).c1), _z, (ctx).c0); \
    (dst) = fmaf(fmaf(-(ctx).M0t, _e, (ctx).M0t), rcpf(fmaf(-(ctx).cosfa, _e, 1.f)), (ctx).bse); \
} while (0)

template <int NPAIRS>
__device__ __forceinline__ void run_aligned(const PixCtx& ctx,
                                            const ulonglong2* __restrict__ s_pc,
                                            const u64* __restrict__ s_ex,
                                            u64 dmask, int NP,
                                            float* optr, size_t stp)
{
    const u64 ONE = pack2(1.f, 1.f);
    const u64 R = ctx.R;
    const u64 R2 = mul2(R, R), R6 = mul2(mul2(R2, R2), R2);
    u64 G6 = fma2(R, ONE, ONE);
    G6 = fma2(G6, R, ONE); G6 = fma2(G6, R, ONE);
    G6 = fma2(G6, R, ONE); G6 = fma2(G6, R, ONE);            // 1+r+..+r^5
    u64 H6 = fma2(R, ONE, pack2(2.f, 2.f));
    H6 = fma2(H6, R, pack2(3.f, 3.f)); H6 = fma2(H6, R, pack2(4.f, 4.f));
    H6 = fma2(H6, R, pack2(5.f, 5.f)); H6 = fma2(H6, R, pack2(6.f, 6.f)); // Σ i·r^(6-i)

    float sig0; SIG_OF(ctx, 0ull, sig0);
    optr[0] = sig0; optr[stp] = sig0; optr[2 * stp] = sig0;
    optr += 3 * stp;

    const u64 dm = dmask >> 3;                 // bit 0 -> output j=3
    u64 S = s_pc[0].x;                         // dup'd aif[30]

    #pragma unroll 8
    for (int k = 0; k < NPAIRS; ++k) {
        const ulonglong2 p0 = s_pc[2 * k];     // {(A,A),(sl,sl)} — one LDS.128
        const ulonglong2 p1 = s_pc[2 * k + 1];
        S = fma2(S, R6, fma2(p0.y, H6, mul2(p0.x, G6)));
        const u64 Sx = fma2(S, R, s_ex[k + 3]);
        const u64 Se = ((dm >> k) & 1ull) ? Sx : S;   // branchless select
        float sig; SIG_OF(ctx, Se, sig);
        *optr = sig; optr += stp;
        S = fma2(S, R6, fma2(p1.y, H6, mul2(p1.x, G6)));
    }
    const ulonglong2 pn = s_pc[NP - 1];
    S = fma2(S, R6, fma2(pn.y, H6, mul2(pn.x, G6)));
    const u64 Sx = fma2(S, R, s_ex[NPAIRS + 3]);
    const u64 Se = ((dm >> NPAIRS) & 1ull) ? Sx : S;
    float sigl; SIG_OF(ctx, Se, sigl);
    *optr = sigl;
}

// ---------------------------------------------------------------------------
// Single fused kernel: per-block lightweight prep + per-pixel closed-form run
// ---------------------------------------------------------------------------
__global__ void __launch_bounds__(TPB)
dce_kernel(const float* __restrict__ param,
           const float* __restrict__ sample_time,
           const float* __restrict__ Cp,
           float* __restrict__ out, int npix, int ns)
{
    __shared__ float s_st[MAXNS], s_cp[MAXNS];
    __shared__ __align__(16) ulonglong2 s_pc[MAXNP];  // {(A,A),(sl,sl)}
    __shared__ u64   s_ex[MAXNS];
    __shared__ float s_av[MAXNP + 1];
    __shared__ int   s_idx[MAXNS];
    __shared__ int   s_ok;
    __shared__ unsigned int s_dm[2];
    __shared__ float s_aif[MAXL];                     // fallback only

    const int tid = threadIdx.x;
    if (tid == 0) { s_ok = 1; s_dm[0] = 0; s_dm[1] = 0; }
    for (int j = tid; j < ns && j < MAXNS; j += TPB) { s_st[j] = sample_time[j]; s_cp[j] = Cp[j]; }
    __syncthreads();

    const int Ltrue = (int)llrint((double)s_st[ns - 1] / 0.1) + 1;
    const int L = Ltrue < MAXL ? Ltrue : MAXL;

    // searchsorted (identical IEEE ops to jnp) + d_j classification
    for (int j = tid; j < ns && j < MAXNS; j += TPB) {
        const float st = s_st[j];
        int lo = 0, hi = L;
        while (lo < hi) { int mid = (lo + hi) >> 1; if ((float)mid * STEPF < st) lo = mid + 1; else hi = mid; }
        lo = lo < (L - 1) ? lo : (L - 1);
        s_idx[j] = lo;
        const int d = lo - 12 * j;
        if (d < 0 || d > 1) atomicAnd(&s_ok, 0);
        else if (d == 1) atomicOr(&s_dm[j >> 5], 1u << (j & 31));
    }
    __syncthreads();

    const int NP = 2 * ns - 7;
    const int aligned = s_ok && ns >= 5 && ns <= MAXNS && NP < MAXNP && Ltrue == 12 * (ns - 1) + 1;

    if (aligned) {
        for (int i = tid; i <= NP; i += TPB)
            s_av[i] = interp_at((float)(6 * i) * STEPF, s_st, s_cp, ns);
        __syncthreads();
        for (int i = tid; i < NP; i += TPB) {
            const float A = s_av[i];
            const float sl = (s_av[i + 1] - A) * (1.f / 6.f);
            ulonglong2 q; q.x = dup2(A); q.y = dup2(sl);
            s_pc[i] = q;
        }
        for (int j = tid; j < ns && j < MAXNS; j += TPB) {
            const int m = 12 * j + 1;
            float v = 0.f;
            if (m >= DELAY_N && m < L) v = interp_at((float)(m - DELAY_N) * STEPF, s_st, s_cp, ns);
            s_ex[j] = dup2(v);
        }
    } else {
        for (int i = tid; i < L; i += TPB)
            s_aif[i] = (i >= DELAY_N) ? interp_at((float)(i - DELAY_N) * STEPF, s_st, s_cp, ns) : 0.f;
    }
    __syncthreads();

    const u64 dmask = ((u64)s_dm[1] << 32) | (u64)s_dm[0];

    const int pix = blockIdx.x * TPB + tid;
    if (pix >= npix) return;

    // ---- per-pixel pharmacokinetic constants ----
    const float ve  = param[pix];
    const float vp  = param[npix + pix];
    const float fpp = param[2 * npix + pix];
    const float ps  = param[3 * npix + pix];

    const float Te = ve / ps;
    const float T  = (vp + ve) / fpp;
    const float Tc = vp / fpp;
    const float s  = T + Te;
    const float disc = sqrtf(fmaxf(s * s - 4.f * Tc * Te, 0.f));
    const float inv2 = 1.f / (2.f * Tc * Te);
    const float thp = (s + disc) * inv2;
    const float thm = (s - disc) * inv2;

    const float rm = expf(-thm * STEPF);
    const float rp = expf(-thp * STEPF);
    const float Lf = (float)L;
    const float SEm = (-expm1f(-thm * STEPF * Lf)) / (-expm1f(-thm * STEPF));
    const float SEp = (-expm1f(-thp * STEPF * Lf)) / (-expm1f(-thp * STEPF));

    const float cmv = 1.f - Te * thm;
    const float cpc = Te * thp - 1.f;
    const float inv_she = 1.f / (SEm - SEp);
    const float inv_shp = 1.f / fmaf(cmv, SEm, cpc * SEp);
    const float alpha = vp * inv_shp * cmv + ve * inv_she;
    const float beta  = vp * inv_shp * cpc - ve * inv_she;
    const float Kz    = -(0.00487f * 4.3f);

    PixCtx ctx;
    ctx.R   = pack2(rm, rp);
    ctx.ZAB = pack2(Kz * alpha, Kz * beta);
    ctx.cosfa = 0.98480775301220806f;
    const float E1 = expf(-0.00487f);
    ctx.M0t = 100.f * (1.f - ctx.cosfa * E1) / (1.f - E1);
    ctx.bse = 100.f - ctx.M0t * (1.f - E1) / (1.f - E1 * ctx.cosfa);
    ctx.c0 = E1; ctx.c1 = E1; ctx.c2 = E1 * 0.5f; ctx.c3 = E1 * (1.f / 6.f);

    float* optr = out + pix;
    const size_t stp = (size_t)npix;

    if (aligned) {
        const int npairs = ns - 4;
        if (npairs == 46) {
            run_aligned<46>(ctx, s_pc, s_ex, dmask, NP, optr, stp);
        } else {
            // generic aligned loop (runtime trip count)
            const u64 ONE = pack2(1.f, 1.f);
            const u64 R = ctx.R;
            const u64 R2 = mul2(R, R), R6 = mul2(mul2(R2, R2), R2);
            u64 G6 = fma2(R, ONE, ONE);
            G6 = fma2(G6, R, ONE); G6 = fma2(G6, R, ONE);
            G6 = fma2(G6, R, ONE); G6 = fma2(G6, R, ONE);
            u64 H6 = fma2(R, ONE, pack2(2.f, 2.f));
            H6 = fma2(H6, R, pack2(3.f, 3.f)); H6 = fma2(H6, R, pack2(4.f, 4.f));
            H6 = fma2(H6, R, pack2(5.f, 5.f)); H6 = fma2(H6, R, pack2(6.f, 6.f));

            float sig0; SIG_OF(ctx, 0ull, sig0);
            optr[0] = sig0; optr[stp] = sig0; optr[2 * stp] = sig0;
            optr += 3 * stp;

            u64 dm = dmask >> 3;
            u64 S = s_pc[0].x;
            for (int k = 0; k < npairs; ++k) {
                const ulonglong2 p0 = s_pc[2 * k];
                const ulonglong2 p1 = s_pc[2 * k + 1];
                S = fma2(S, R6, fma2(p0.y, H6, mul2(p0.x, G6)));
                const u64 Sx = fma2(S, R, s_ex[k + 3]);
                const u64 Se = (dm & 1ull) ? Sx : S;
                dm >>= 1;
                float sig; SIG_OF(ctx, Se, sig);
                *optr = sig; optr += stp;
                S = fma2(S, R6, fma2(p1.y, H6, mul2(p1.x, G6)));
            }
            const ulonglong2 pn = s_pc[NP - 1];
            S = fma2(S, R6, fma2(pn.y, H6, mul2(pn.x, G6)));
            const u64 Sx = fma2(S, R, s_ex[ns - 1]);
            const u64 Se = (dm & 1ull) ? Sx : S;
            float sigl; SIG_OF(ctx, Se, sigl);
            *optr = sigl;
        }
    } else {
        // fallback: proven unit-step recurrence
        u64 S = 0ull;
        int m = 0;
        for (int j = 0; j < ns; ++j) {
            const int target = s_idx[j];
            #pragma unroll 4
            for (; m <= target; ++m) S = fma2(S, ctx.R, dup2(s_aif[m]));
            float sig; SIG_OF(ctx, S, sig);
            *optr = sig; optr += stp;
        }
    }
}

extern "C" void kernel_launch(void* const* d_in, const int* in_sizes, int n_in,
                              void* d_out, int out_size)
{
    const float* param       = (const float*)d_in[0];
    const float* sample_time = (const float*)d_in[1];
    const float* Cp          = (const float*)d_in[2];
    float* out = (float*)d_out;

    const int ns   = in_sizes[1];
    const int npix = in_sizes[0] / 4;

    dce_kernel<<<(npix + TPB - 1) / TPB, TPB>>>(param, sample_time, Cp, out, npix, ns);
}

// round 11
// speedup vs baseline: 1.1366x; 1.1214x over previous
#include <cuda_runtime.h>
#include <math.h>

#define STEPF   0.1f
#define MAXL    2048
#define MAXNS   64
#define MAXNP   128
#define DELAY_N 30
#define TPB     128

typedef unsigned long long u64;

__device__ __forceinline__ u64 fma2(u64 a, u64 b, u64 c) {
    u64 d; asm("fma.rn.f32x2 %0, %1, %2, %3;" : "=l"(d) : "l"(a), "l"(b), "l"(c)); return d;
}
__device__ __forceinline__ u64 mul2(u64 a, u64 b) {
    u64 d; asm("mul.rn.f32x2 %0, %1, %2;" : "=l"(d) : "l"(a), "l"(b)); return d;
}
__device__ __forceinline__ u64 pack2(float lo, float hi) {
    u64 d; asm("mov.b64 %0, {%1, %2};" : "=l"(d) : "f"(lo), "f"(hi)); return d;
}
__device__ __forceinline__ u64 dup2(float v) { return pack2(v, v); }
__device__ __forceinline__ void unpack2(u64 v, float& lo, float& hi) {
    asm("mov.b64 {%0, %1}, %2;" : "=f"(lo), "=f"(hi) : "l"(v));
}
__device__ __forceinline__ float rcpf(float x) {
    float r; asm("rcp.approx.f32 %0, %1;" : "=f"(r) : "f"(x)); return r;
}

// full binary-search interp (reference-equivalent), used as fallback
__device__ __noinline__ float interp_full(float t, const float* st, const float* cp, int ns) {
    if (t <= st[0]) return cp[0];
    if (t >= st[ns - 1]) return cp[ns - 1];
    int lo = 0, hi = ns - 1;
    while (lo + 1 < hi) { int mid = (lo + hi) >> 1; if (st[mid] <= t) lo = mid; else hi = mid; }
    return cp[lo] + (t - st[lo]) * (cp[lo + 1] - cp[lo]) / (st[lo + 1] - st[lo]);
}

// guessed-bracket interp: same result as interp_full, ~10x fewer dependent LDS
__device__ __forceinline__ float interp_guess(float t, int guess,
                                              const float* st, const float* cp, int ns) {
    if (t <= st[0]) return cp[0];
    if (t >= st[ns - 1]) return cp[ns - 1];
    int lo = guess < 0 ? 0 : (guess > ns - 2 ? ns - 2 : guess);
    if (!(st[lo] <= t && t < st[lo + 1])) {
        if (lo > 0 && st[lo - 1] <= t && t < st[lo]) --lo;
        else if (lo < ns - 2 && st[lo + 1] <= t && t < st[lo + 2]) ++lo;
        else return interp_full(t, st, cp, ns);
    }
    return cp[lo] + (t - st[lo]) * (cp[lo + 1] - cp[lo]) / (st[lo + 1] - st[lo]);
}

struct PixCtx {
    u64 R, ZAB;
    float d0, d1, d2, d3;     // Horner coeffs of u = 1 - c*E1*exp_taylor(z)
    float K1, K2;             // sig = K1 + K2 * rcp(u)
};

#define SIG_OF(ctx, Sv, dst) do {                                              \
    float _zl, _zh; unpack2(mul2((Sv), (ctx).ZAB), _zl, _zh);                  \
    const float _z = _zl + _zh;                                                \
    const float _u = fmaf(fmaf(fmaf(_z, (ctx).d3, (ctx).d2), _z, (ctx).d1), _z, (ctx).d0); \
    (dst) = fmaf((ctx).K2, rcpf(_u), (ctx).K1);                                \
} while (0)

template <int NPAIRS>
__device__ __forceinline__ void run_aligned(const PixCtx& ctx,
                                            const ulonglong2* __restrict__ s_pc,
                                            const u64* __restrict__ s_ex,
                                            u64 dmask, int NP,
                                            float* optr, size_t stp)
{
    const u64 ONE = pack2(1.f, 1.f);
    const u64 R = ctx.R;
    const u64 R2 = mul2(R, R), R6 = mul2(mul2(R2, R2), R2);
    u64 G6 = fma2(R, ONE, ONE);
    G6 = fma2(G6, R, ONE); G6 = fma2(G6, R, ONE);
    G6 = fma2(G6, R, ONE); G6 = fma2(G6, R, ONE);            // 1+r+..+r^5
    u64 H6 = fma2(R, ONE, pack2(2.f, 2.f));
    H6 = fma2(H6, R, pack2(3.f, 3.f)); H6 = fma2(H6, R, pack2(4.f, 4.f));
    H6 = fma2(H6, R, pack2(5.f, 5.f)); H6 = fma2(H6, R, pack2(6.f, 6.f)); // Σ i·r^(6-i)

    float sig0; SIG_OF(ctx, 0ull, sig0);
    optr[0] = sig0; optr[stp] = sig0; optr[2 * stp] = sig0;
    optr += 3 * stp;

    const u64 dm = dmask >> 3;                 // bit 0 -> output j=3
    u64 S = s_pc[0].x;                         // dup'd aif[30]

    #pragma unroll 8
    for (int k = 0; k < NPAIRS; ++k) {
        const ulonglong2 p0 = s_pc[2 * k];     // {(A,A),(sl,sl)} — one LDS.128
        const ulonglong2 p1 = s_pc[2 * k + 1];
        S = fma2(S, R6, fma2(p0.y, H6, mul2(p0.x, G6)));
        const u64 Sx = fma2(S, R, s_ex[k + 3]);
        const u64 Se = ((dm >> k) & 1ull) ? Sx : S;   // branchless select
        float sig; SIG_OF(ctx, Se, sig);
        *optr = sig; optr += stp;
        S = fma2(S, R6, fma2(p1.y, H6, mul2(p1.x, G6)));
    }
    const ulonglong2 pn = s_pc[NP - 1];
    S = fma2(S, R6, fma2(pn.y, H6, mul2(pn.x, G6)));
    const u64 Sx = fma2(S, R, s_ex[NPAIRS + 3]);
    const u64 Se = ((dm >> NPAIRS) & 1ull) ? Sx : S;
    float sigl; SIG_OF(ctx, Se, sigl);
    *optr = sigl;
}

// ---------------------------------------------------------------------------
__global__ void __launch_bounds__(TPB)
dce_kernel(const float* __restrict__ param,
           const float* __restrict__ sample_time,
           const float* __restrict__ Cp,
           float* __restrict__ out, int npix, int ns)
{
    __shared__ float s_st[MAXNS], s_cp[MAXNS];
    __shared__ __align__(16) ulonglong2 s_pc[MAXNP];  // {(A,A),(sl,sl)}
    __shared__ u64   s_ex[MAXNS];
    __shared__ float s_av[MAXNP + 1];
    __shared__ int   s_idx[MAXNS];
    __shared__ int   s_ok;
    __shared__ unsigned int s_dm[2];
    __shared__ float s_aif[MAXL];                     // fallback only

    const int tid = threadIdx.x;
    if (tid == 0) { s_ok = 1; s_dm[0] = 0; s_dm[1] = 0; }
    for (int j = tid; j < ns && j < MAXNS; j += TPB) { s_st[j] = sample_time[j]; s_cp[j] = Cp[j]; }
    __syncthreads();

    const int Ltrue = (int)llrint((double)s_st[ns - 1] / 0.1) + 1;
    const int L = Ltrue < MAXL ? Ltrue : MAXL;

    // searchsorted with verified guess (candidates 12j / 12j+1), binary fallback
    for (int j = tid; j < ns && j < MAXNS; j += TPB) {
        const float st = s_st[j];
        const int c = 12 * j;
        int lo = -1;
        if (c < L && !((float)c * STEPF < st)) {              // t[c] >= st
            if (c == 0 || ((float)(c - 1) * STEPF < st)) lo = c;
        } else if (c < L) {                                   // t[c] < st
            if (c + 1 >= L) lo = L - 1;                       // result L, clamped
            else if (!((float)(c + 1) * STEPF < st)) lo = c + 1;
        }
        if (lo < 0) {                                         // full binary search
            int a = 0, b = L;
            while (a < b) { int mid = (a + b) >> 1; if ((float)mid * STEPF < st) a = mid + 1; else b = mid; }
            lo = a < (L - 1) ? a : (L - 1);
        }
        s_idx[j] = lo;
        const int d = lo - 12 * j;
        if (d < 0 || d > 1) atomicAnd(&s_ok, 0);
        else if (d == 1) atomicOr(&s_dm[j >> 5], 1u << (j & 31));
    }
    __syncthreads();

    const int NP = 2 * ns - 7;
    const int aligned = s_ok && ns >= 5 && ns <= MAXNS && NP < MAXNP && Ltrue == 12 * (ns - 1) + 1;

    if (aligned) {
        for (int i = tid; i <= NP; i += TPB)
            s_av[i] = interp_guess((float)(6 * i) * STEPF, i >> 1, s_st, s_cp, ns);
        __syncthreads();
        for (int i = tid; i < NP; i += TPB) {
            const float A = s_av[i];
            const float sl = (s_av[i + 1] - A) * (1.f / 6.f);
            ulonglong2 q; q.x = dup2(A); q.y = dup2(sl);
            s_pc[i] = q;
        }
        for (int j = tid; j < ns && j < MAXNS; j += TPB) {
            const int m = 12 * j + 1;
            float v = 0.f;
            if (m >= DELAY_N && m < L)
                v = interp_guess((float)(m - DELAY_N) * STEPF, (m - DELAY_N) / 12, s_st, s_cp, ns);
            s_ex[j] = dup2(v);
        }
    } else {
        for (int i = tid; i < L; i += TPB)
            s_aif[i] = (i >= DELAY_N) ? interp_full((float)(i - DELAY_N) * STEPF, s_st, s_cp, ns) : 0.f;
    }
    __syncthreads();

    const u64 dmask = ((u64)s_dm[1] << 32) | (u64)s_dm[0];

    const int pix = blockIdx.x * TPB + tid;
    if (pix >= npix) return;

    // ---- per-pixel pharmacokinetic constants ----
    const float ve  = param[pix];
    const float vp  = param[npix + pix];
    const float fpp = param[2 * npix + pix];
    const float ps  = param[3 * npix + pix];

    const float Te = ve / ps;
    const float T  = (vp + ve) / fpp;
    const float Tc = vp / fpp;
    const float s  = T + Te;
    const float disc = sqrtf(fmaxf(s * s - 4.f * Tc * Te, 0.f));
    const float inv2 = 1.f / (2.f * Tc * Te);
    const float thp = (s + disc) * inv2;
    const float thm = (s - disc) * inv2;

    const float rm = expf(-thm * STEPF);
    const float rp = expf(-thp * STEPF);
    const float Lf = (float)L;
    const float SEm = (-expm1f(-thm * STEPF * Lf)) / (-expm1f(-thm * STEPF));
    const float SEp = (-expm1f(-thp * STEPF * Lf)) / (-expm1f(-thp * STEPF));

    const float cmv = 1.f - Te * thm;
    const float cpc = Te * thp - 1.f;
    const float inv_she = 1.f / (SEm - SEp);
    const float inv_shp = 1.f / fmaf(cmv, SEm, cpc * SEp);
    const float alpha = vp * inv_shp * cmv + ve * inv_she;
    const float beta  = vp * inv_shp * cpc - ve * inv_she;
    const float Kz    = -(0.00487f * 4.3f);

    PixCtx ctx;
    ctx.R   = pack2(rm, rp);
    ctx.ZAB = pack2(Kz * alpha, Kz * beta);
    {
        const float c  = 0.98480775301220806f;     // cos(10 deg)
        const float E1 = expf(-0.00487f);
        const float M0t = 100.f * (1.f - c * E1) / (1.f - E1);
        const float bse = 100.f - M0t * (1.f - E1) / (1.f - E1 * c);
        const float q = c * E1;
        ctx.d0 = 1.f - q; ctx.d1 = -q; ctx.d2 = -q * 0.5f; ctx.d3 = -q * (1.f / 6.f);
        ctx.K1 = bse + M0t / c;
        ctx.K2 = M0t * (c - 1.f) / c;
    }

    float* optr = out + pix;
    const size_t stp = (size_t)npix;

    if (aligned) {
        const int npairs = ns - 4;
        if (npairs == 46) {
            run_aligned<46>(ctx, s_pc, s_ex, dmask, NP, optr, stp);
        } else {
            const u64 ONE = pack2(1.f, 1.f);
            const u64 R = ctx.R;
            const u64 R2 = mul2(R, R), R6 = mul2(mul2(R2, R2), R2);
            u64 G6 = fma2(R, ONE, ONE);
            G6 = fma2(G6, R, ONE); G6 = fma2(G6, R, ONE);
            G6 = fma2(G6, R, ONE); G6 = fma2(G6, R, ONE);
            u64 H6 = fma2(R, ONE, pack2(2.f, 2.f));
            H6 = fma2(H6, R, pack2(3.f, 3.f)); H6 = fma2(H6, R, pack2(4.f, 4.f));
            H6 = fma2(H6, R, pack2(5.f, 5.f)); H6 = fma2(H6, R, pack2(6.f, 6.f));

            float sig0; SIG_OF(ctx, 0ull, sig0);
            optr[0] = sig0; optr[stp] = sig0; optr[2 * stp] = sig0;
            optr += 3 * stp;

            u64 dm = dmask >> 3;
            u64 S = s_pc[0].x;
            for (int k = 0; k < npairs; ++k) {
                const ulonglong2 p0 = s_pc[2 * k];
                const ulonglong2 p1 = s_pc[2 * k + 1];
                S = fma2(S, R6, fma2(p0.y, H6, mul2(p0.x, G6)));
                const u64 Sx = fma2(S, R, s_ex[k + 3]);
                const u64 Se = (dm & 1ull) ? Sx : S;
                dm >>= 1;
                float sig; SIG_OF(ctx, Se, sig);
                *optr = sig; optr += stp;
                S = fma2(S, R6, fma2(p1.y, H6, mul2(p1.x, G6)));
            }
            const ulonglong2 pn = s_pc[NP - 1];
            S = fma2(S, R6, fma2(pn.y, H6, mul2(pn.x, G6)));
            const u64 Sx = fma2(S, R, s_ex[ns - 1]);
            const u64 Se = (dm & 1ull) ? Sx : S;
            float sigl; SIG_OF(ctx, Se, sigl);
            *optr = sigl;
        }
    } else {
        // fallback: proven unit-step recurrence
        u64 S = 0ull;
        int m = 0;
        for (int j = 0; j < ns; ++j) {
            const int target = s_idx[j];
            #pragma unroll 4
            for (; m <= target; ++m) S = fma2(S, ctx.R, dup2(s_aif[m]));
            float sig; SIG_OF(ctx, S, sig);
            *optr = sig; optr += stp;
        }
    }
}

extern "C" void kernel_launch(void* const* d_in, const int* in_sizes, int n_in,
                              void* d_out, int out_size)
{
    const float* param       = (const float*)d_in[0];
    const float* sample_time = (const float*)d_in[1];
    const float* Cp          = (const float*)d_in[2];
    float* out = (float*)d_out;

    const int ns   = in_sizes[1];
    const int npix = in_sizes[0] / 4;

    dce_kernel<<<(npix + TPB - 1) / TPB, TPB>>>(param, sample_time, Cp, out, npix, ns);
}

// round 12
// speedup vs baseline: 1.1388x; 1.0019x over previous
#include <cuda_runtime.h>
#include <math.h>

#define STEPF   0.1f
#define MAXL    2048
#define MAXNS   64
#define MAXNP   128
#define DELAY_N 30
#define TPB     128

typedef unsigned long long u64;

__device__ __forceinline__ u64 fma2(u64 a, u64 b, u64 c) {
    u64 d; asm("fma.rn.f32x2 %0, %1, %2, %3;" : "=l"(d) : "l"(a), "l"(b), "l"(c)); return d;
}
__device__ __forceinline__ u64 mul2(u64 a, u64 b) {
    u64 d; asm("mul.rn.f32x2 %0, %1, %2;" : "=l"(d) : "l"(a), "l"(b)); return d;
}
__device__ __forceinline__ u64 pack2(float lo, float hi) {
    u64 d; asm("mov.b64 %0, {%1, %2};" : "=l"(d) : "f"(lo), "f"(hi)); return d;
}
__device__ __forceinline__ u64 dup2(float v) { return pack2(v, v); }
__device__ __forceinline__ void unpack2(u64 v, float& lo, float& hi) {
    asm("mov.b64 {%0, %1}, %2;" : "=f"(lo), "=f"(hi) : "l"(v));
}
__device__ __forceinline__ float rcpf(float x) {
    float r; asm("rcp.approx.f32 %0, %1;" : "=f"(r) : "f"(x)); return r;
}

// full binary-search interp (reference-equivalent), fallback
__device__ __noinline__ float interp_full(float t, const float* st, const float* cp, int ns) {
    if (t <= st[0]) return cp[0];
    if (t >= st[ns - 1]) return cp[ns - 1];
    int lo = 0, hi = ns - 1;
    while (lo + 1 < hi) { int mid = (lo + hi) >> 1; if (st[mid] <= t) lo = mid; else hi = mid; }
    return cp[lo] + (t - st[lo]) * (cp[lo + 1] - cp[lo]) / (st[lo + 1] - st[lo]);
}

// guessed-bracket interp: identical result, ~10x fewer dependent LDS
__device__ __forceinline__ float interp_guess(float t, int guess,
                                              const float* st, const float* cp, int ns) {
    if (t <= st[0]) return cp[0];
    if (t >= st[ns - 1]) return cp[ns - 1];
    int lo = guess < 0 ? 0 : (guess > ns - 2 ? ns - 2 : guess);
    if (!(st[lo] <= t && t < st[lo + 1])) {
        if (lo > 0 && st[lo - 1] <= t && t < st[lo]) --lo;
        else if (lo < ns - 2 && st[lo + 1] <= t && t < st[lo + 2]) ++lo;
        else return interp_full(t, st, cp, ns);
    }
    return cp[lo] + (t - st[lo]) * (cp[lo + 1] - cp[lo]) / (st[lo + 1] - st[lo]);
}

struct PixCtx {
    u64 R, Rm1, ZAB;
    float d0, d1, d2, d3;     // Horner coeffs of u = 1 - c*E1*exp_taylor(z)
    float K1, K2;             // sig = K1 + K2 * rcp(u)
};

#define SIG_OF(ctx, Sv, dst) do {                                              \
    float _zl, _zh; unpack2(mul2((Sv), (ctx).ZAB), _zl, _zh);                  \
    const float _z = _zl + _zh;                                                \
    const float _u = fmaf(fmaf(fmaf(_z, (ctx).d3, (ctx).d2), _z, (ctx).d1), _z, (ctx).d0); \
    (dst) = fmaf((ctx).K2, rcpf(_u), (ctx).K1);                                \
} while (0)

template <int NPAIRS>
__device__ __forceinline__ void run_aligned(const PixCtx& ctx,
                                            const ulonglong2* __restrict__ s_pc,
                                            const ulonglong2* __restrict__ s_exq,
                                            int NP, float* optr, size_t stp)
{
    const u64 ONE = pack2(1.f, 1.f);
    const u64 R = ctx.R;
    const u64 R2 = mul2(R, R), R6 = mul2(mul2(R2, R2), R2);
    u64 G6 = fma2(R, ONE, ONE);
    G6 = fma2(G6, R, ONE); G6 = fma2(G6, R, ONE);
    G6 = fma2(G6, R, ONE); G6 = fma2(G6, R, ONE);            // 1+r+..+r^5
    u64 H6 = fma2(R, ONE, pack2(2.f, 2.f));
    H6 = fma2(H6, R, pack2(3.f, 3.f)); H6 = fma2(H6, R, pack2(4.f, 4.f));
    H6 = fma2(H6, R, pack2(5.f, 5.f)); H6 = fma2(H6, R, pack2(6.f, 6.f)); // Σ i·r^(6-i)

    float sig0; SIG_OF(ctx, 0ull, sig0);
    optr[0] = sig0; optr[stp] = sig0; optr[2 * stp] = sig0;
    optr += 3 * stp;

    u64 S = s_pc[0].x;                         // dup'd aif[30]

    #pragma unroll 8
    for (int k = 0; k < NPAIRS; ++k) {
        const ulonglong2 p0 = s_pc[2 * k];     // {(A,A),(sl,sl)} — one LDS.128
        const ulonglong2 p1 = s_pc[2 * k + 1];
        const ulonglong2 eq = s_exq[k + 3];    // {(flag,flag),(exf,exf)}
        S = fma2(S, R6, fma2(p0.y, H6, mul2(p0.x, G6)));
        const u64 W  = fma2(eq.x, ctx.Rm1, ONE);      // 1 + flag*(r-1)
        const u64 Se = fma2(S, W, eq.y);              // S*r^flag + flag*ex
        float sig; SIG_OF(ctx, Se, sig);
        *optr = sig; optr += stp;
        S = fma2(S, R6, fma2(p1.y, H6, mul2(p1.x, G6)));
    }
    const ulonglong2 pn = s_pc[NP - 1];
    const ulonglong2 eq = s_exq[NPAIRS + 3];
    S = fma2(S, R6, fma2(pn.y, H6, mul2(pn.x, G6)));
    const u64 W  = fma2(eq.x, ctx.Rm1, ONE);
    const u64 Se = fma2(S, W, eq.y);
    float sigl; SIG_OF(ctx, Se, sigl);
    *optr = sigl;
}

// ---------------------------------------------------------------------------
__global__ void __launch_bounds__(TPB, 1)
dce_kernel(const float* __restrict__ param,
           const float* __restrict__ sample_time,
           const float* __restrict__ Cp,
           float* __restrict__ out, int npix, int ns)
{
    __shared__ float s_st[MAXNS], s_cp[MAXNS];
    __shared__ __align__(16) ulonglong2 s_pc[MAXNP];   // {(A,A),(sl,sl)}
    __shared__ __align__(16) ulonglong2 s_exq[MAXNS];  // {(flag,flag),(exf,exf)}
    __shared__ float s_av[MAXNP + 1];
    __shared__ int   s_idx[MAXNS];
    __shared__ int   s_ok;
    __shared__ float s_aif[MAXL];                      // fallback only

    const int tid = threadIdx.x;
    if (tid == 0) s_ok = 1;
    for (int j = tid; j < ns && j < MAXNS; j += TPB) { s_st[j] = sample_time[j]; s_cp[j] = Cp[j]; }
    __syncthreads();

    const int Ltrue = (int)llrint((double)s_st[ns - 1] / 0.1) + 1;
    const int L = Ltrue < MAXL ? Ltrue : MAXL;

    // searchsorted with verified guess (candidates 12j / 12j+1), binary fallback
    for (int j = tid; j < ns && j < MAXNS; j += TPB) {
        const float st = s_st[j];
        const int c = 12 * j;
        int lo = -1;
        if (c < L && !((float)c * STEPF < st)) {
            if (c == 0 || ((float)(c - 1) * STEPF < st)) lo = c;
        } else if (c < L) {
            if (c + 1 >= L) lo = L - 1;
            else if (!((float)(c + 1) * STEPF < st)) lo = c + 1;
        }
        if (lo < 0) {
            int a = 0, b = L;
            while (a < b) { int mid = (a + b) >> 1; if ((float)mid * STEPF < st) a = mid + 1; else b = mid; }
            lo = a < (L - 1) ? a : (L - 1);
        }
        s_idx[j] = lo;
        const int d = lo - 12 * j;
        if (d < 0 || d > 1) atomicAnd(&s_ok, 0);
    }
    __syncthreads();

    const int NP = 2 * ns - 7;
    const int aligned = s_ok && ns >= 5 && ns <= MAXNS && NP < MAXNP && Ltrue == 12 * (ns - 1) + 1;

    if (aligned) {
        for (int i = tid; i <= NP; i += TPB)
            s_av[i] = interp_guess((float)(6 * i) * STEPF, i >> 1, s_st, s_cp, ns);
        __syncthreads();
        for (int i = tid; i < NP; i += TPB) {
            const float A = s_av[i];
            const float sl = (s_av[i + 1] - A) * (1.f / 6.f);
            ulonglong2 q; q.x = dup2(A); q.y = dup2(sl);
            s_pc[i] = q;
        }
        for (int j = tid; j < ns && j < MAXNS; j += TPB) {
            const int d = s_idx[j] - 12 * j;           // 0 or 1
            const int m = 12 * j + 1;
            float exf = 0.f;
            if (d == 1 && m >= DELAY_N && m < L)
                exf = interp_guess((float)(m - DELAY_N) * STEPF, (m - DELAY_N) / 12, s_st, s_cp, ns);
            ulonglong2 q; q.x = dup2((float)d); q.y = dup2(exf);
            s_exq[j] = q;
        }
    } else {
        for (int i = tid; i < L; i += TPB)
            s_aif[i] = (i >= DELAY_N) ? interp_full((float)(i - DELAY_N) * STEPF, s_st, s_cp, ns) : 0.f;
    }
    __syncthreads();

    const int pix = blockIdx.x * TPB + tid;
    if (pix >= npix) return;

    // ---- per-pixel pharmacokinetic constants ----
    const float ve  = param[pix];
    const float vp  = param[npix + pix];
    const float fpp = param[2 * npix + pix];
    const float ps  = param[3 * npix + pix];

    const float Te = ve / ps;
    const float T  = (vp + ve) / fpp;
    const float Tc = vp / fpp;
    const float s  = T + Te;
    const float disc = sqrtf(fmaxf(s * s - 4.f * Tc * Te, 0.f));
    const float inv2 = 1.f / (2.f * Tc * Te);
    const float thp = (s + disc) * inv2;
    const float thm = (s - disc) * inv2;

    const float rm = expf(-thm * STEPF);
    const float rp = expf(-thp * STEPF);
    const float Lf = (float)L;
    const float SEm = (-expm1f(-thm * STEPF * Lf)) / (-expm1f(-thm * STEPF));
    const float SEp = (-expm1f(-thp * STEPF * Lf)) / (-expm1f(-thp * STEPF));

    const float cmv = 1.f - Te * thm;
    const float cpc = Te * thp - 1.f;
    const float inv_she = 1.f / (SEm - SEp);
    const float inv_shp = 1.f / fmaf(cmv, SEm, cpc * SEp);
    const float alpha = vp * inv_shp * cmv + ve * inv_she;
    const float beta  = vp * inv_shp * cpc - ve * inv_she;
    const float Kz    = -(0.00487f * 4.3f);

    PixCtx ctx;
    ctx.R    = pack2(rm, rp);
    ctx.Rm1  = pack2(rm - 1.f, rp - 1.f);
    ctx.ZAB  = pack2(Kz * alpha, Kz * beta);
    {
        const float c  = 0.98480775301220806f;     // cos(10 deg)
        const float E1 = expf(-0.00487f);
        const float M0t = 100.f * (1.f - c * E1) / (1.f - E1);
        const float bse = 100.f - M0t * (1.f - E1) / (1.f - E1 * c);
        const float q = c * E1;
        ctx.d0 = 1.f - q; ctx.d1 = -q; ctx.d2 = -q * 0.5f; ctx.d3 = -q * (1.f / 6.f);
        ctx.K1 = bse + M0t / c;
        ctx.K2 = M0t * (c - 1.f) / c;
    }

    float* optr = out + pix;
    const size_t stp = (size_t)npix;

    if (aligned) {
        const int npairs = ns - 4;
        if (npairs == 46) {
            run_aligned<46>(ctx, s_pc, s_exq, NP, optr, stp);
        } else {
            // generic aligned loop (runtime trip count)
            const u64 ONE = pack2(1.f, 1.f);
            const u64 R = ctx.R;
            const u64 R2 = mul2(R, R), R6 = mul2(mul2(R2, R2), R2);
            u64 G6 = fma2(R, ONE, ONE);
            G6 = fma2(G6, R, ONE); G6 = fma2(G6, R, ONE);
            G6 = fma2(G6, R, ONE); G6 = fma2(G6, R, ONE);
            u64 H6 = fma2(R, ONE, pack2(2.f, 2.f));
            H6 = fma2(H6, R, pack2(3.f, 3.f)); H6 = fma2(H6, R, pack2(4.f, 4.f));
            H6 = fma2(H6, R, pack2(5.f, 5.f)); H6 = fma2(H6, R, pack2(6.f, 6.f));

            float sig0; SIG_OF(ctx, 0ull, sig0);
            optr[0] = sig0; optr[stp] = sig0; optr[2 * stp] = sig0;
            optr += 3 * stp;

            u64 S = s_pc[0].x;
            for (int k = 0; k < npairs; ++k) {
                const ulonglong2 p0 = s_pc[2 * k];
                const ulonglong2 p1 = s_pc[2 * k + 1];
                const ulonglong2 eq = s_exq[k + 3];
                S = fma2(S, R6, fma2(p0.y, H6, mul2(p0.x, G6)));
                const u64 W  = fma2(eq.x, ctx.Rm1, ONE);
                const u64 Se = fma2(S, W, eq.y);
                float sig; SIG_OF(ctx, Se, sig);
                *optr = sig; optr += stp;
                S = fma2(S, R6, fma2(p1.y, H6, mul2(p1.x, G6)));
            }
            const ulonglong2 pn = s_pc[NP - 1];
            const ulonglong2 eq = s_exq[ns - 1];
            S = fma2(S, R6, fma2(pn.y, H6, mul2(pn.x, G6)));
            const u64 W  = fma2(eq.x, ctx.Rm1, ONE);
            const u64 Se = fma2(S, W, eq.y);
            float sigl; SIG_OF(ctx, Se, sigl);
            *optr = sigl;
        }
    } else {
        // fallback: proven unit-step recurrence
        u64 S = 0ull;
        int m = 0;
        for (int j = 0; j < ns; ++j) {
            const int target = s_idx[j];
            #pragma unroll 4
            for (; m <= target; ++m) S = fma2(S, ctx.R, dup2(s_aif[m]));
            float sig; SIG_OF(ctx, S, sig);
            *optr = sig; optr += stp;
        }
    }
}

extern "C" void kernel_launch(void* const* d_in, const int* in_sizes, int n_in,
                              void* d_out, int out_size)
{
    const float* param       = (const float*)d_in[0];
    const float* sample_time = (const float*)d_in[1];
    const float* Cp          = (const float*)d_in[2];
    float* out = (float*)d_out;

    const int ns   = in_sizes[1];
    const int npix = in_sizes[0] / 4;

    dce_kernel<<<(npix + TPB - 1) / TPB, TPB>>>(param, sample_time, Cp, out, npix, ns);
}

// round 13
// speedup vs baseline: 1.2611x; 1.1074x over previous
#include <cuda_runtime.h>
#include <math.h>

#define STEPF   0.1f
#define MAXL    2048
#define MAXNS   64
#define MAXNP   128
#define DELAY_N 30
#define TPB     128

typedef unsigned long long u64;

__device__ __forceinline__ u64 fma2(u64 a, u64 b, u64 c) {
    u64 d; asm("fma.rn.f32x2 %0, %1, %2, %3;" : "=l"(d) : "l"(a), "l"(b), "l"(c)); return d;
}
__device__ __forceinline__ u64 mul2(u64 a, u64 b) {
    u64 d; asm("mul.rn.f32x2 %0, %1, %2;" : "=l"(d) : "l"(a), "l"(b)); return d;
}
__device__ __forceinline__ u64 pack2(float lo, float hi) {
    u64 d; asm("mov.b64 %0, {%1, %2};" : "=l"(d) : "f"(lo), "f"(hi)); return d;
}
__device__ __forceinline__ u64 dup2(float v) { return pack2(v, v); }
__device__ __forceinline__ void unpack2(u64 v, float& lo, float& hi) {
    asm("mov.b64 {%0, %1}, %2;" : "=f"(lo), "=f"(hi) : "l"(v));
}
__device__ __forceinline__ float rcpf(float x) {
    float r; asm("rcp.approx.f32 %0, %1;" : "=f"(r) : "f"(x)); return r;
}

// full binary-search interp (reference-equivalent), fallback
__device__ __noinline__ float interp_full(float t, const float* st, const float* cp, int ns) {
    if (t <= st[0]) return cp[0];
    if (t >= st[ns - 1]) return cp[ns - 1];
    int lo = 0, hi = ns - 1;
    while (lo + 1 < hi) { int mid = (lo + hi) >> 1; if (st[mid] <= t) lo = mid; else hi = mid; }
    return cp[lo] + (t - st[lo]) * (cp[lo + 1] - cp[lo]) / (st[lo + 1] - st[lo]);
}

// guessed-bracket interp: identical result, ~10x fewer dependent LDS
__device__ __forceinline__ float interp_guess(float t, int guess,
                                              const float* st, const float* cp, int ns) {
    if (t <= st[0]) return cp[0];
    if (t >= st[ns - 1]) return cp[ns - 1];
    int lo = guess < 0 ? 0 : (guess > ns - 2 ? ns - 2 : guess);
    if (!(st[lo] <= t && t < st[lo + 1])) {
        if (lo > 0 && st[lo - 1] <= t && t < st[lo]) --lo;
        else if (lo < ns - 2 && st[lo + 1] <= t && t < st[lo + 2]) ++lo;
        else return interp_full(t, st, cp, ns);
    }
    return cp[lo] + (t - st[lo]) * (cp[lo + 1] - cp[lo]) / (st[lo + 1] - st[lo]);
}

struct PixCtx {
    u64 R, Rm1, ZAB;
    float d0, d1, d2, d3;     // Horner coeffs of u = 1 - c*E1*exp_taylor(z)
    float K1, K2;             // sig = K1 + K2 * rcp(u)
};

#define SIG_OF(ctx, Sv, dst) do {                                              \
    float _zl, _zh; unpack2(mul2((Sv), (ctx).ZAB), _zl, _zh);                  \
    const float _z = _zl + _zh;                                                \
    const float _u = fmaf(fmaf(fmaf(_z, (ctx).d3, (ctx).d2), _z, (ctx).d1), _z, (ctx).d0); \
    (dst) = fmaf((ctx).K2, rcpf(_u), (ctx).K1);                                \
} while (0)

template <int NPAIRS>
__device__ __forceinline__ void run_aligned(const PixCtx& ctx,
                                            const ulonglong2* __restrict__ s_pc,
                                            const ulonglong2* __restrict__ s_exq,
                                            int NP, float* optr, size_t stp)
{
    const u64 ONE = pack2(1.f, 1.f);
    const u64 R = ctx.R;
    const u64 R2 = mul2(R, R), R6 = mul2(mul2(R2, R2), R2);
    u64 G6 = fma2(R, ONE, ONE);
    G6 = fma2(G6, R, ONE); G6 = fma2(G6, R, ONE);
    G6 = fma2(G6, R, ONE); G6 = fma2(G6, R, ONE);            // 1+r+..+r^5
    u64 H6 = fma2(R, ONE, pack2(2.f, 2.f));
    H6 = fma2(H6, R, pack2(3.f, 3.f)); H6 = fma2(H6, R, pack2(4.f, 4.f));
    H6 = fma2(H6, R, pack2(5.f, 5.f)); H6 = fma2(H6, R, pack2(6.f, 6.f)); // Σ i·r^(6-i)

    float sig0; SIG_OF(ctx, 0ull, sig0);
    optr[0] = sig0; optr[stp] = sig0; optr[2 * stp] = sig0;
    optr += 3 * stp;

    u64 S = s_pc[0].x;                         // dup'd aif[30]

    #pragma unroll 16
    for (int k = 0; k < NPAIRS; ++k) {
        const ulonglong2 p0 = s_pc[2 * k];     // {(A,A),(sl,sl)} — one LDS.128
        const ulonglong2 p1 = s_pc[2 * k + 1];
        const ulonglong2 eq = s_exq[k + 3];    // {(flag,flag),(exf,exf)}
        S = fma2(S, R6, fma2(p0.y, H6, mul2(p0.x, G6)));
        const u64 W  = fma2(eq.x, ctx.Rm1, ONE);      // 1 + flag*(r-1)
        const u64 Se = fma2(S, W, eq.y);              // S*r^flag + flag*ex
        float sig; SIG_OF(ctx, Se, sig);
        *optr = sig; optr += stp;
        S = fma2(S, R6, fma2(p1.y, H6, mul2(p1.x, G6)));
    }
    const ulonglong2 pn = s_pc[NP - 1];
    const ulonglong2 eq = s_exq[NPAIRS + 3];
    S = fma2(S, R6, fma2(pn.y, H6, mul2(pn.x, G6)));
    const u64 W  = fma2(eq.x, ctx.Rm1, ONE);
    const u64 Se = fma2(S, W, eq.y);
    float sigl; SIG_OF(ctx, Se, sigl);
    *optr = sigl;
}

// ---------------------------------------------------------------------------
__global__ void __launch_bounds__(TPB, 6)
dce_kernel(const float* __restrict__ param,
           const float* __restrict__ sample_time,
           const float* __restrict__ Cp,
           float* __restrict__ out, int npix, int ns)
{
    __shared__ float s_st[MAXNS], s_cp[MAXNS];
    __shared__ __align__(16) ulonglong2 s_pc[MAXNP];   // {(A,A),(sl,sl)}
    __shared__ __align__(16) ulonglong2 s_exq[MAXNS];  // {(flag,flag),(exf,exf)}
    __shared__ float s_av[MAXNP + 1];
    __shared__ int   s_idx[MAXNS];
    __shared__ int   s_ok;
    __shared__ float s_aif[MAXL];                      // fallback only

    const int tid = threadIdx.x;
    if (tid == 0) s_ok = 1;
    for (int j = tid; j < ns && j < MAXNS; j += TPB) { s_st[j] = sample_time[j]; s_cp[j] = Cp[j]; }
    __syncthreads();

    const int Ltrue = (int)llrint((double)s_st[ns - 1] / 0.1) + 1;
    const int L = Ltrue < MAXL ? Ltrue : MAXL;

    // searchsorted with verified guess (candidates 12j / 12j+1), binary fallback
    for (int j = tid; j < ns && j < MAXNS; j += TPB) {
        const float st = s_st[j];
        const int c = 12 * j;
        int lo = -1;
        if (c < L && !((float)c * STEPF < st)) {
            if (c == 0 || ((float)(c - 1) * STEPF < st)) lo = c;
        } else if (c < L) {
            if (c + 1 >= L) lo = L - 1;
            else if (!((float)(c + 1) * STEPF < st)) lo = c + 1;
        }
        if (lo < 0) {
            int a = 0, b = L;
            while (a < b) { int mid = (a + b) >> 1; if ((float)mid * STEPF < st) a = mid + 1; else b = mid; }
            lo = a < (L - 1) ? a : (L - 1);
        }
        s_idx[j] = lo;
        const int d = lo - 12 * j;
        if (d < 0 || d > 1) atomicAnd(&s_ok, 0);
    }
    __syncthreads();

    const int NP = 2 * ns - 7;
    const int aligned = s_ok && ns >= 5 && ns <= MAXNS && NP < MAXNP && Ltrue == 12 * (ns - 1) + 1;

    if (aligned) {
        for (int i = tid; i <= NP; i += TPB)
            s_av[i] = interp_guess((float)(6 * i) * STEPF, i >> 1, s_st, s_cp, ns);
        __syncthreads();
        for (int i = tid; i < NP; i += TPB) {
            const float A = s_av[i];
            const float sl = (s_av[i + 1] - A) * (1.f / 6.f);
            ulonglong2 q; q.x = dup2(A); q.y = dup2(sl);
            s_pc[i] = q;
        }
        for (int j = tid; j < ns && j < MAXNS; j += TPB) {
            const int d = s_idx[j] - 12 * j;           // 0 or 1
            const int m = 12 * j + 1;
            float exf = 0.f;
            if (d == 1 && m >= DELAY_N && m < L)
                exf = interp_guess((float)(m - DELAY_N) * STEPF, (m - DELAY_N) / 12, s_st, s_cp, ns);
            ulonglong2 q; q.x = dup2((float)d); q.y = dup2(exf);
            s_exq[j] = q;
        }
    } else {
        for (int i = tid; i < L; i += TPB)
            s_aif[i] = (i >= DELAY_N) ? interp_full((float)(i - DELAY_N) * STEPF, s_st, s_cp, ns) : 0.f;
    }
    __syncthreads();

    const int pix = blockIdx.x * TPB + tid;
    if (pix >= npix) return;

    // ---- per-pixel pharmacokinetic constants (fast-math divisions: error
    //      analysis in journal — rcp.approx 2e-7 rel err is invisible at 1e-3 tol) ----
    const float ve  = param[pix];
    const float vp  = param[npix + pix];
    const float fpp = param[2 * npix + pix];
    const float ps  = param[3 * npix + pix];

    const float rfpp = rcpf(fpp);
    const float Te = ve * rcpf(ps);
    const float T  = (vp + ve) * rfpp;
    const float Tc = vp * rfpp;
    const float s  = T + Te;
    const float disc = sqrtf(fmaxf(s * s - 4.f * Tc * Te, 0.f));
    const float inv2 = rcpf(2.f * Tc * Te);
    const float thp = (s + disc) * inv2;
    const float thm = (s - disc) * inv2;

    const float rm = expf(-thm * STEPF);
    const float rp = expf(-thp * STEPF);
    const float Lf = (float)L;
    const float SEm = (-expm1f(-thm * STEPF * Lf)) * rcpf(-expm1f(-thm * STEPF));
    const float SEp = (-expm1f(-thp * STEPF * Lf)) * rcpf(-expm1f(-thp * STEPF));

    const float cmv = 1.f - Te * thm;
    const float cpc = Te * thp - 1.f;
    const float inv_she = rcpf(SEm - SEp);
    const float inv_shp = rcpf(fmaf(cmv, SEm, cpc * SEp));
    const float alpha = vp * inv_shp * cmv + ve * inv_she;
    const float beta  = vp * inv_shp * cpc - ve * inv_she;
    const float Kz    = -(0.00487f * 4.3f);

    PixCtx ctx;
    ctx.R    = pack2(rm, rp);
    ctx.Rm1  = pack2(rm - 1.f, rp - 1.f);
    ctx.ZAB  = pack2(Kz * alpha, Kz * beta);
    {
        const float c  = 0.98480775301220806f;     // cos(10 deg)
        const float E1 = expf(-0.00487f);
        const float M0t = 100.f * __fdividef(1.f - c * E1, 1.f - E1);
        const float bse = 100.f - M0t * __fdividef(1.f - E1, 1.f - E1 * c);
        const float q = c * E1;
        ctx.d0 = 1.f - q; ctx.d1 = -q; ctx.d2 = -q * 0.5f; ctx.d3 = -q * (1.f / 6.f);
        const float rc = rcpf(c);
        ctx.K1 = bse + M0t * rc;
        ctx.K2 = M0t * (c - 1.f) * rc;
    }

    float* optr = out + pix;
    const size_t stp = (size_t)npix;

    if (aligned) {
        const int npairs = ns - 4;
        if (npairs == 46) {
            run_aligned<46>(ctx, s_pc, s_exq, NP, optr, stp);
        } else {
            // generic aligned loop (runtime trip count)
            const u64 ONE = pack2(1.f, 1.f);
            const u64 R = ctx.R;
            const u64 R2 = mul2(R, R), R6 = mul2(mul2(R2, R2), R2);
            u64 G6 = fma2(R, ONE, ONE);
            G6 = fma2(G6, R, ONE); G6 = fma2(G6, R, ONE);
            G6 = fma2(G6, R, ONE); G6 = fma2(G6, R, ONE);
            u64 H6 = fma2(R, ONE, pack2(2.f, 2.f));
            H6 = fma2(H6, R, pack2(3.f, 3.f)); H6 = fma2(H6, R, pack2(4.f, 4.f));
            H6 = fma2(H6, R, pack2(5.f, 5.f)); H6 = fma2(H6, R, pack2(6.f, 6.f));

            float sig0; SIG_OF(ctx, 0ull, sig0);
            optr[0] = sig0; optr[stp] = sig0; optr[2 * stp] = sig0;
            optr += 3 * stp;

            u64 S = s_pc[0].x;
            for (int k = 0; k < npairs; ++k) {
                const ulonglong2 p0 = s_pc[2 * k];
                const ulonglong2 p1 = s_pc[2 * k + 1];
                const ulonglong2 eq = s_exq[k + 3];
                S = fma2(S, R6, fma2(p0.y, H6, mul2(p0.x, G6)));
                const u64 W  = fma2(eq.x, ctx.Rm1, ONE);
                const u64 Se = fma2(S, W, eq.y);
                float sig; SIG_OF(ctx, Se, sig);
                *optr = sig; optr += stp;
                S = fma2(S, R6, fma2(p1.y, H6, mul2(p1.x, G6)));
            }
            const ulonglong2 pn = s_pc[NP - 1];
            const ulonglong2 eq = s_exq[ns - 1];
            S = fma2(S, R6, fma2(pn.y, H6, mul2(pn.x, G6)));
            const u64 W  = fma2(eq.x, ctx.Rm1, ONE);
            const u64 Se = fma2(S, W, eq.y);
            float sigl; SIG_OF(ctx, Se, sigl);
            *optr = sigl;
        }
    } else {
        // fallback: proven unit-step recurrence
        u64 S = 0ull;
        int m = 0;
        for (int j = 0; j < ns; ++j) {
            const int target = s_idx[j];
            #pragma unroll 4
            for (; m <= target; ++m) S = fma2(S, ctx.R, dup2(s_aif[m]));
            float sig; SIG_OF(ctx, S, sig);
            *optr = sig; optr += stp;
        }
    }
}

extern "C" void kernel_launch(void* const* d_in, const int* in_sizes, int n_in,
                              void* d_out, int out_size)
{
    const float* param       = (const float*)d_in[0];
    const float* sample_time = (const float*)d_in[1];
    const float* Cp          = (const float*)d_in[2];
    float* out = (float*)d_out;

    const int ns   = in_sizes[1];
    const int npix = in_sizes[0] / 4;

    dce_kernel<<<(npix + TPB - 1) / TPB, TPB>>>(param, sample_time, Cp, out, npix, ns);
}